// round 1
// baseline (speedup 1.0000x reference)
#include <cuda_runtime.h>
#include <math.h>

#define Bb 64
#define Nn 1024
#define Dd 512
#define TOT (Bb*Nn*Dd)
#define NUMIT 4
#define EPSc 1e-8f

// Scratch (device globals — no runtime allocation allowed)
__device__ float g_z[TOT];                 // ADMM dual z (B,N,D)
__device__ float g_logs[TOT];              // log_s       (B,N,D)
__device__ float g_m[NUMIT][Bb*Dd];        // log_mu stage used by row-kernel k
__device__ float g_e[NUMIT][Bb*Nn];        // log_eta stage used by col-kernel k

__device__ __forceinline__ float warpMax(float v){
#pragma unroll
    for (int o = 16; o > 0; o >>= 1) v = fmaxf(v, __shfl_xor_sync(0xffffffffu, v, o));
    return v;
}
__device__ __forceinline__ float warpSum(float v){
#pragma unroll
    for (int o = 16; o > 0; o >>= 1) v += __shfl_xor_sync(0xffffffffu, v, o);
    return v;
}

// ---------------------------------------------------------------------------
// Precompute the full log_mu / log_eta trajectories.
// Key identity: z1 = A[b,d] - Bv[b,n]; the Bv part cancels inside the
// d-axis logsumexp, so log_mu stays (B,D):
//   g = (rho*m + a2*logp0 - A)/(rho+a2);  m' = g - lse_d(g);  A += rho*exp(m')
// Symmetric for log_eta over N with a3 and C. One block per batch.
// ---------------------------------------------------------------------------
__global__ void __launch_bounds__(512) precomp_kernel(
    const float* __restrict__ p0, const float* __restrict__ q0,
    const float* __restrict__ a2, const float* __restrict__ a3,
    const float* __restrict__ rho)
{
    __shared__ float red[32];
    int b = blockIdx.x, tid = threadIdx.x;
    int wid = tid >> 5, lane = tid & 31;

    // ---- mu chain: D=512, one element per thread ----
    float lp = logf(p0[b*Dd + tid]);
    float m = lp, A = 0.f;
    g_m[0][b*Dd + tid] = lp;
    for (int kk = 0; kk < NUMIT-1; kk++){
        float r = rho[kk], a = a2[kk];
        float g = (r*m + a*lp - A) / (r + a);
        float v = warpMax(g);
        if (lane == 0) red[wid] = v;
        __syncthreads();
        if (wid == 0){ float u = (lane < 16) ? red[lane] : -3.4e38f; u = warpMax(u); if (lane==0) red[16]=u; }
        __syncthreads();
        float mx = red[16];
        __syncthreads();
        float s = warpSum(expf(g - mx));
        if (lane == 0) red[wid] = s;
        __syncthreads();
        if (wid == 0){ float u = (lane < 16) ? red[lane] : 0.f; u = warpSum(u); if (lane==0) red[16]=u; }
        __syncthreads();
        float L = mx + logf(red[16]);
        __syncthreads();
        m = g - L;
        A += r * expf(m);
        g_m[kk+1][b*Dd + tid] = m;
    }

    // ---- eta chain: N=1024, two elements per thread ----
    float lq0 = logf(q0[b*Nn + tid] + EPSc);
    float lq1 = logf(q0[b*Nn + tid + 512] + EPSc);
    float e0 = lq0, e1 = lq1, C0 = 0.f, C1 = 0.f;
    g_e[0][b*Nn + tid]       = e0;
    g_e[0][b*Nn + tid + 512] = e1;
    for (int kk = 0; kk < NUMIT-1; kk++){
        float r = rho[kk], a = a3[kk];
        float h0 = (r*e0 + a*lq0 - C0) / (r + a);
        float h1 = (r*e1 + a*lq1 - C1) / (r + a);
        float v = warpMax(fmaxf(h0, h1));
        if (lane == 0) red[wid] = v;
        __syncthreads();
        if (wid == 0){ float u = (lane < 16) ? red[lane] : -3.4e38f; u = warpMax(u); if (lane==0) red[16]=u; }
        __syncthreads();
        float mx = red[16];
        __syncthreads();
        float s = warpSum(expf(h0 - mx) + expf(h1 - mx));
        if (lane == 0) red[wid] = s;
        __syncthreads();
        if (wid == 0){ float u = (lane < 16) ? red[lane] : 0.f; u = warpSum(u); if (lane==0) red[16]=u; }
        __syncthreads();
        float L = mx + logf(red[16]);
        __syncthreads();
        e0 = h0 - L; e1 = h1 - L;
        C0 += r * expf(e0); C1 += r * expf(e1);
        g_e[kk+1][b*Nn + tid]       = e0;
        g_e[kk+1][b*Nn + tid + 512] = e1;
    }
}

// ---------------------------------------------------------------------------
// Row kernel: T-update. One block per (b,n) row; 128 threads x float4 = D=512.
//   y = (x - z)/rho + log_s ;  log_t = m - lse_d(y) + y
// FIRST: z=0, log_s = log(q0*p0 + eps) computed on the fly.
// LAST : write exp(log_t)*mask (final output); otherwise write log_t.
// ---------------------------------------------------------------------------
template<bool FIRST, bool LAST>
__global__ void __launch_bounds__(128) row_kernel(
    const float* __restrict__ x, const float* __restrict__ p0,
    const float* __restrict__ q0, const float* __restrict__ mask,
    const float* __restrict__ rho, float* __restrict__ logt, int k)
{
    __shared__ float red[8];
    int row = blockIdx.x;
    int b = row >> 10;                       // row / N
    int tid = threadIdx.x;
    int wid = tid >> 5, lane = tid & 31;
    size_t base = (size_t)row * Dd;

    float r = __ldg(rho + k), invr = 1.f / r;
    float4 xv = ((const float4*)(x + base))[tid];
    float4 mv = ((const float4*)(g_m[k] + (size_t)b*Dd))[tid];
    float4 y;
    if (FIRST){
        float q = __ldg(q0 + row);
        float4 pv = ((const float4*)(p0 + (size_t)b*Dd))[tid];
        y.x = xv.x*invr + logf(q*pv.x + EPSc);
        y.y = xv.y*invr + logf(q*pv.y + EPSc);
        y.z = xv.z*invr + logf(q*pv.z + EPSc);
        y.w = xv.w*invr + logf(q*pv.w + EPSc);
    } else {
        float4 zv = ((const float4*)(g_z + base))[tid];
        float4 sv = ((const float4*)(g_logs + base))[tid];
        y.x = (xv.x - zv.x)*invr + sv.x;
        y.y = (xv.y - zv.y)*invr + sv.y;
        y.z = (xv.z - zv.z)*invr + sv.z;
        y.w = (xv.w - zv.w)*invr + sv.w;
    }

    // block logsumexp over 512 values (4 warps)
    float mx = fmaxf(fmaxf(y.x, y.y), fmaxf(y.z, y.w));
    mx = warpMax(mx);
    if (lane == 0) red[wid] = mx;
    __syncthreads();
    if (wid == 0){ float u = (lane < 4) ? red[lane] : -3.4e38f; u = warpMax(u); if (lane==0) red[4]=u; }
    __syncthreads();
    mx = red[4];
    float se = expf(y.x-mx) + expf(y.y-mx) + expf(y.z-mx) + expf(y.w-mx);
    se = warpSum(se);
    if (lane == 0) red[wid] = se;
    __syncthreads();
    if (wid == 0){ float u = (lane < 4) ? red[lane] : 0.f; u = warpSum(u); if (lane==0) red[5]=u; }
    __syncthreads();
    float L = mx + logf(red[5]);

    float4 lt;
    lt.x = mv.x + y.x - L;
    lt.y = mv.y + y.y - L;
    lt.z = mv.z + y.z - L;
    lt.w = mv.w + y.w - L;
    if (LAST){
        float mk = __ldg(mask + row);
        lt.x = expf(lt.x)*mk; lt.y = expf(lt.y)*mk;
        lt.z = expf(lt.z)*mk; lt.w = expf(lt.w)*mk;
    }
    ((float4*)(logt + base))[tid] = lt;
}

// ---------------------------------------------------------------------------
// Column kernel: S-update + z-update. Block covers (b, 32 d-columns),
// 256 threads = 8 n-rows in flight, fully coalesced 128B/warp.
//   y2 = (z + rho*log_t)/(a1+rho);  log_s = e - lse_n(y2) + y2
//   z'  = z + rho*(exp(log_t) - exp(log_s))*mask
// Pass 1: online LSE down each column. Pass 2 (reverse n for L2 reuse):
// finalize and write log_s, z.
// ---------------------------------------------------------------------------
template<bool FIRST>
__global__ void __launch_bounds__(256) col_kernel(
    const float* __restrict__ mask, const float* __restrict__ rho,
    const float* __restrict__ a1, const float* __restrict__ logt, int k)
{
    __shared__ float s_e[Nn];
    __shared__ float s_mk[Nn];
    __shared__ float s_mx[256];
    __shared__ float s_sm[256];
    __shared__ float s_M2[32];

    int b = blockIdx.y;
    int tid = threadIdx.x;
    int dc = tid & 31, nr = tid >> 5;
    int d = blockIdx.x * 32 + dc;

    float r = __ldg(rho + k);
    float inv = 1.f / (__ldg(a1 + k) + r);

    for (int i = tid; i < Nn; i += 256){
        s_e[i]  = g_e[k][b*Nn + i];
        s_mk[i] = mask[b*Nn + i];
    }
    __syncthreads();

    size_t cb = (size_t)b * Nn * Dd + d;

    // pass 1: online logsumexp down the column (stride 8 in n per thread)
    float mx = -3.4e38f, sm = 0.f;
    for (int n = nr; n < Nn; n += 8){
        size_t idx = cb + (size_t)n * Dd;
        float lt = logt[idx];
        float zv = FIRST ? 0.f : g_z[idx];
        float v = (zv + r*lt) * inv;
        if (v > mx){ sm = sm * expf(mx - v) + 1.f; mx = v; }
        else       { sm += expf(v - mx); }
    }
    s_mx[tid] = mx; s_sm[tid] = sm;
    __syncthreads();
    if (tid < 32){
        float M = s_mx[tid], S = s_sm[tid];
#pragma unroll
        for (int j = 1; j < 8; j++){
            float M2_ = s_mx[j*32 + tid], S2 = s_sm[j*32 + tid];
            float nm = fmaxf(M, M2_);
            S = S * expf(M - nm) + S2 * expf(M2_ - nm);
            M = nm;
        }
        s_M2[tid] = M + logf(S);
    }
    __syncthreads();
    float M2 = s_M2[dc];

    // pass 2 (reverse n order: tail of pass 1 is still warm in L2)
    for (int n = (Nn - 8) + nr; n >= 0; n -= 8){
        size_t idx = cb + (size_t)n * Dd;
        float lt = logt[idx];
        float zv = FIRST ? 0.f : g_z[idx];
        float v = (zv + r*lt) * inv;
        float ls = s_e[n] - M2 + v;
        float mk = s_mk[n];
        float t = expf(lt) * mk;
        float s = expf(ls) * mk;
        g_logs[idx] = ls;
        g_z[idx]    = zv + r * (t - s);
    }
}

// ---------------------------------------------------------------------------
extern "C" void kernel_launch(void* const* d_in, const int* in_sizes, int n_in,
                              void* d_out, int out_size)
{
    const float* x    = (const float*)d_in[0];
    const float* p0   = (const float*)d_in[1];
    const float* q0   = (const float*)d_in[2];
    const float* a1   = (const float*)d_in[3];
    const float* a2   = (const float*)d_in[4];
    const float* a3   = (const float*)d_in[5];
    const float* rho  = (const float*)d_in[6];
    const float* mask = (const float*)d_in[7];
    float* out = (float*)d_out;   // doubles as the log_t buffer between passes

    precomp_kernel<<<Bb, 512>>>(p0, q0, a2, a3, rho);

    dim3 cgrid(Dd / 32, Bb);
    // iter 0
    row_kernel<true,  false><<<Bb*Nn, 128>>>(x, p0, q0, mask, rho, out, 0);
    col_kernel<true ><<<cgrid, 256>>>(mask, rho, a1, out, 0);
    // iter 1
    row_kernel<false, false><<<Bb*Nn, 128>>>(x, p0, q0, mask, rho, out, 1);
    col_kernel<false><<<cgrid, 256>>>(mask, rho, a1, out, 1);
    // iter 2
    row_kernel<false, false><<<Bb*Nn, 128>>>(x, p0, q0, mask, rho, out, 2);
    col_kernel<false><<<cgrid, 256>>>(mask, rho, a1, out, 2);
    // iter 3: only the T-update affects the output
    row_kernel<false, true ><<<Bb*Nn, 128>>>(x, p0, q0, mask, rho, out, 3);
}